// round 1
// baseline (speedup 1.0000x reference)
#include <cuda_runtime.h>
#include <math.h>

// ---------------- problem constants ----------------
#define Dm   1024
#define Hh   16
#define DH   64
#define DFF  4096
#define DC   768
#define Tt   2048
#define Bb   2
#define Cc   77
#define MX   4096          // Bb*Tt rows of x

// ---------------- scratch (static device arrays; no allocs) ----------------
__device__ float g_ln   [(size_t)MX * Dm];          // 16 MB, reused for ln1/ln2/ln3
__device__ float g_qkv  [(size_t)MX * 3 * Dm];      // 48 MB
__device__ float g_scores[(size_t)Bb * Hh * Tt * Tt]; // 1 GB
__device__ float g_attn [(size_t)MX * Dm];          // attn out (SA, then CA)
__device__ float g_x1   [(size_t)MX * Dm];
__device__ float g_x2   [(size_t)MX * Dm];
__device__ float g_qca  [(size_t)MX * Dm];
__device__ float g_kvca [(size_t)Bb * Cc * 2 * Dm];
__device__ float g_csc  [(size_t)Bb * Hh * Tt * Cc]; // ~20 MB
__device__ float g_ff   [(size_t)MX * DFF];         // 64 MB

// ---------------- reductions ----------------
__device__ __forceinline__ float block_sum(float v, float* sh) {
    #pragma unroll
    for (int o = 16; o > 0; o >>= 1) v += __shfl_xor_sync(0xffffffffu, v, o);
    int w = threadIdx.x >> 5;
    if ((threadIdx.x & 31) == 0) sh[w] = v;
    __syncthreads();
    if (threadIdx.x < 32) {
        float t = (threadIdx.x < 8) ? sh[threadIdx.x] : 0.f;
        #pragma unroll
        for (int o = 4; o > 0; o >>= 1) t += __shfl_xor_sync(0xffffffffu, t, o);
        if (threadIdx.x == 0) sh[0] = t;
    }
    __syncthreads();
    float r = sh[0];
    __syncthreads();
    return r;
}

__device__ __forceinline__ float block_max(float v, float* sh) {
    #pragma unroll
    for (int o = 16; o > 0; o >>= 1) v = fmaxf(v, __shfl_xor_sync(0xffffffffu, v, o));
    int w = threadIdx.x >> 5;
    if ((threadIdx.x & 31) == 0) sh[w] = v;
    __syncthreads();
    if (threadIdx.x < 32) {
        float t = (threadIdx.x < 8) ? sh[threadIdx.x] : -3.0e38f;
        #pragma unroll
        for (int o = 4; o > 0; o >>= 1) t = fmaxf(t, __shfl_xor_sync(0xffffffffu, t, o));
        if (threadIdx.x == 0) sh[0] = t;
    }
    __syncthreads();
    float r = sh[0];
    __syncthreads();
    return r;
}

// ---------------- LayerNorm: one block per row, 256 thr, D=1024 ----------------
__global__ __launch_bounds__(256) void ln_kernel(
    const float* __restrict__ x, const float* __restrict__ g,
    const float* __restrict__ b, float* __restrict__ out)
{
    __shared__ float sh[8];
    long row = blockIdx.x;
    const float4* xr = (const float4*)(x + row * Dm);
    int tid = threadIdx.x;
    float4 v = xr[tid];
    float s = v.x + v.y + v.z + v.w;
    s = block_sum(s, sh);
    float mean = s * (1.0f / Dm);
    float dx = v.x - mean, dy = v.y - mean, dz = v.z - mean, dw = v.w - mean;
    float s2 = dx*dx + dy*dy + dz*dz + dw*dw;
    s2 = block_sum(s2, sh);
    float rstd = rsqrtf(s2 * (1.0f / Dm) + 1e-5f);
    float4 gg = ((const float4*)g)[tid];
    float4 bbv = ((const float4*)b)[tid];
    float4 o;
    o.x = dx * rstd * gg.x + bbv.x;
    o.y = dy * rstd * gg.y + bbv.y;
    o.z = dz * rstd * gg.z + bbv.z;
    o.w = dw * rstd * gg.w + bbv.w;
    ((float4*)(out + row * Dm))[tid] = o;
}

// ---------------- row softmax (optionally causal), in place ----------------
__global__ __launch_bounds__(256) void softmax_kernel(
    float* __restrict__ S, int L, int Trows, int causal)
{
    __shared__ float sh[8];
    int row = blockIdx.x;
    float* sr = S + (long)row * L;
    int t = row % Trows;
    int valid = causal ? (t + 1) : L;
    int tid = threadIdx.x;

    float m = -3.0e38f;
    for (int j = tid; j < valid; j += 256) m = fmaxf(m, sr[j]);
    m = block_max(m, sh);

    float sum = 0.f;
    for (int j = tid; j < valid; j += 256) {
        float e = __expf(sr[j] - m);
        sr[j] = e;
        sum += e;
    }
    sum = block_sum(sum, sh);
    float inv = 1.0f / sum;

    for (int j = tid; j < L; j += 256) {
        if (j < valid) sr[j] *= inv;
        else           sr[j] = 0.f;
    }
}

// ---------------- generic batched SGEMM with fused epilogue ----------------
// C[r,c] = epi( alpha * sum_k A[r,k]*B[k,c] )
// EPI bits: 1=+bias[c], 4=GELU(exact), 2=+Res[r*ldc+c]
// batch z -> (bb = z/Hn, hh = z%Hn); per-matrix offsets bb*s?b + hh*s?h
#define BM 128
#define BN 128
#define BKk 8
#define TMm 8
#define TNn 8

template<int EPI, bool TRB>
__global__ __launch_bounds__(256) void gemm_kernel(
    const float* __restrict__ A, const float* __restrict__ Bm,
    const float* __restrict__ bias, const float* __restrict__ Res,
    float* __restrict__ C,
    int M, int N, int K, int lda, int ldb, int ldc,
    long sAb, long sAh, long sBb, long sBh, long sCb, long sCh,
    int Hn, float alpha)
{
    __shared__ float As[BKk][BM];
    __shared__ float Bs[BKk][BN];

    int z = blockIdx.z;
    int zb = z / Hn, zh = z - zb * Hn;
    A  += zb * sAb + zh * sAh;
    Bm += zb * sBb + zh * sBh;
    C  += zb * sCb + zh * sCh;

    int tid = threadIdx.x;
    int tx = tid & 15, ty = tid >> 4;
    int row0 = blockIdx.y * BM, col0 = blockIdx.x * BN;

    int arow = tid >> 1;        // 0..127
    int ak0  = (tid & 1) * 4;   // 0 or 4
    int brow = tid >> 5;        // 0..7
    int bn0  = (tid & 31) * 4;  // 0..124

    float acc[TMm][TNn];
    #pragma unroll
    for (int i = 0; i < TMm; i++)
        #pragma unroll
        for (int j = 0; j < TNn; j++) acc[i][j] = 0.f;

    for (int k0 = 0; k0 < K; k0 += BKk) {
        int gr = row0 + arow;
        #pragma unroll
        for (int i = 0; i < 4; i++) {
            int gk = k0 + ak0 + i;
            float v = 0.f;
            if (gr < M && gk < K) v = A[(long)gr * lda + gk];
            As[ak0 + i][arow] = v;
        }
        {
            int gk = k0 + brow;
            #pragma unroll
            for (int i = 0; i < 4; i++) {
                int gn = col0 + bn0 + i;
                float v = 0.f;
                if (gk < K && gn < N)
                    v = TRB ? Bm[(long)gn * ldb + gk] : Bm[(long)gk * ldb + gn];
                Bs[brow][bn0 + i] = v;
            }
        }
        __syncthreads();

        #pragma unroll
        for (int kk = 0; kk < BKk; kk++) {
            float a[TMm], bfrag[TNn];
            float4 t0 = *(const float4*)&As[kk][ty * TMm];
            float4 t1 = *(const float4*)&As[kk][ty * TMm + 4];
            a[0]=t0.x; a[1]=t0.y; a[2]=t0.z; a[3]=t0.w;
            a[4]=t1.x; a[5]=t1.y; a[6]=t1.z; a[7]=t1.w;
            float4 u0 = *(const float4*)&Bs[kk][tx * TNn];
            float4 u1 = *(const float4*)&Bs[kk][tx * TNn + 4];
            bfrag[0]=u0.x; bfrag[1]=u0.y; bfrag[2]=u0.z; bfrag[3]=u0.w;
            bfrag[4]=u1.x; bfrag[5]=u1.y; bfrag[6]=u1.z; bfrag[7]=u1.w;
            #pragma unroll
            for (int i = 0; i < TMm; i++)
                #pragma unroll
                for (int j = 0; j < TNn; j++)
                    acc[i][j] += a[i] * bfrag[j];
        }
        __syncthreads();
    }

    #pragma unroll
    for (int i = 0; i < TMm; i++) {
        int r = row0 + ty * TMm + i;
        if (r >= M) continue;
        #pragma unroll
        for (int j = 0; j < TNn; j++) {
            int c = col0 + tx * TNn + j;
            if (c >= N) continue;
            float v = acc[i][j] * alpha;
            if (EPI & 1) v += bias[c];
            if (EPI & 4) v = 0.5f * v * (1.0f + erff(v * 0.70710678118654752f));
            if (EPI & 2) v += Res[(long)r * ldc + c];
            C[(long)r * ldc + c] = v;
        }
    }
}

// ---------------- host side ----------------
static inline dim3 ggrid(int M, int N, int Z) {
    return dim3((unsigned)((N + BN - 1) / BN), (unsigned)((M + BM - 1) / BM), (unsigned)Z);
}

extern "C" void kernel_launch(void* const* d_in, const int* in_sizes, int n_in,
                              void* d_out, int out_size)
{
    const float* x        = (const float*)d_in[0];
    const float* cond     = (const float*)d_in[1];
    const float* Wqkv     = (const float*)d_in[2];
    const float* Wproj_sa = (const float*)d_in[3];
    const float* bproj_sa = (const float*)d_in[4];
    const float* g1       = (const float*)d_in[5];
    const float* b1       = (const float*)d_in[6];
    const float* Wq_ca    = (const float*)d_in[7];
    const float* Wkv_ca   = (const float*)d_in[8];
    const float* Wproj_ca = (const float*)d_in[9];
    const float* bproj_ca = (const float*)d_in[10];
    const float* g2       = (const float*)d_in[11];
    const float* b2       = (const float*)d_in[12];
    const float* Wff1     = (const float*)d_in[13];
    const float* bff1     = (const float*)d_in[14];
    const float* Wff2     = (const float*)d_in[15];
    const float* bff2     = (const float*)d_in[16];
    const float* g3       = (const float*)d_in[17];
    const float* b3       = (const float*)d_in[18];
    float* out            = (float*)d_out;

    float *p_ln, *p_qkv, *p_sc, *p_attn, *p_x1, *p_x2, *p_qca, *p_kvca, *p_csc, *p_ff;
    cudaGetSymbolAddress((void**)&p_ln,   g_ln);
    cudaGetSymbolAddress((void**)&p_qkv,  g_qkv);
    cudaGetSymbolAddress((void**)&p_sc,   g_scores);
    cudaGetSymbolAddress((void**)&p_attn, g_attn);
    cudaGetSymbolAddress((void**)&p_x1,   g_x1);
    cudaGetSymbolAddress((void**)&p_x2,   g_x2);
    cudaGetSymbolAddress((void**)&p_qca,  g_qca);
    cudaGetSymbolAddress((void**)&p_kvca, g_kvca);
    cudaGetSymbolAddress((void**)&p_csc,  g_csc);
    cudaGetSymbolAddress((void**)&p_ff,   g_ff);

    const long T3D = (long)Tt * 3 * Dm;     // qkv batch-b stride
    const long TT  = (long)Tt * Tt;
    const long HTT = (long)Hh * TT;
    const long TD  = (long)Tt * Dm;
    const long KVb = (long)Cc * 2 * Dm;     // kv_ca batch-b stride
    const long TC  = (long)Tt * Cc;
    const long HTC = (long)Hh * TC;
    const float iscale = 0.125f;            // DH^-0.5

    // ---- 1) ln1 = LN(x)
    ln_kernel<<<MX, 256>>>(x, g1, b1, p_ln);

    // ---- 2) qkv = ln1 @ Wqkv
    gemm_kernel<0,false><<<ggrid(MX, 3*Dm, 1), 256>>>(
        p_ln, Wqkv, nullptr, nullptr, p_qkv,
        MX, 3*Dm, Dm, Dm, 3*Dm, 3*Dm, 0,0,0,0,0,0, 1, 1.0f);

    // ---- 3) S = scale * Q @ K^T   (batched over b,h)
    gemm_kernel<0,true><<<ggrid(Tt, Tt, Bb*Hh), 256>>>(
        p_qkv, p_qkv + Dm, nullptr, nullptr, p_sc,
        Tt, Tt, DH, 3*Dm, 3*Dm, Tt,
        T3D, DH, T3D, DH, HTT, TT, Hh, iscale);

    // ---- 4) causal softmax rows
    softmax_kernel<<<Bb*Hh*Tt, 256>>>(p_sc, Tt, Tt, 1);

    // ---- 5) attn = P @ V
    gemm_kernel<0,false><<<ggrid(Tt, DH, Bb*Hh), 256>>>(
        p_sc, p_qkv + 2*Dm, nullptr, nullptr, p_attn,
        Tt, DH, Tt, Tt, 3*Dm, Dm,
        HTT, TT, T3D, DH, TD, DH, Hh, 1.0f);

    // ---- 6) x1 = x + attn @ Wproj_sa + bproj_sa
    gemm_kernel<3,false><<<ggrid(MX, Dm, 1), 256>>>(
        p_attn, Wproj_sa, bproj_sa, x, p_x1,
        MX, Dm, Dm, Dm, Dm, Dm, 0,0,0,0,0,0, 1, 1.0f);

    // ---- 7) ln2 = LN(x1)
    ln_kernel<<<MX, 256>>>(p_x1, g2, b2, p_ln);

    // ---- 8) q_ca = ln2 @ Wq_ca
    gemm_kernel<0,false><<<ggrid(MX, Dm, 1), 256>>>(
        p_ln, Wq_ca, nullptr, nullptr, p_qca,
        MX, Dm, Dm, Dm, Dm, Dm, 0,0,0,0,0,0, 1, 1.0f);

    // ---- 9) kv_ca = cond @ Wkv_ca   (flattened (B*C, DC))
    gemm_kernel<0,false><<<ggrid(Bb*Cc, 2*Dm, 1), 256>>>(
        cond, Wkv_ca, nullptr, nullptr, p_kvca,
        Bb*Cc, 2*Dm, DC, DC, 2*Dm, 2*Dm, 0,0,0,0,0,0, 1, 1.0f);

    // ---- 10) Sc = scale * Qca @ Kca^T
    gemm_kernel<0,true><<<ggrid(Tt, Cc, Bb*Hh), 256>>>(
        p_qca, p_kvca, nullptr, nullptr, p_csc,
        Tt, Cc, DH, Dm, 2*Dm, Cc,
        TD, DH, KVb, DH, HTC, TC, Hh, iscale);

    // ---- 11) softmax (non-causal, L=77)
    softmax_kernel<<<Bb*Hh*Tt, 256>>>(p_csc, Cc, Tt, 0);

    // ---- 12) ca_out = Pc @ Vca   (reuse p_attn)
    gemm_kernel<0,false><<<ggrid(Tt, DH, Bb*Hh), 256>>>(
        p_csc, p_kvca + Dm, nullptr, nullptr, p_attn,
        Tt, DH, Cc, Cc, 2*Dm, Dm,
        HTC, TC, KVb, DH, TD, DH, Hh, 1.0f);

    // ---- 13) x2 = x1 + ca_out @ Wproj_ca + bproj_ca
    gemm_kernel<3,false><<<ggrid(MX, Dm, 1), 256>>>(
        p_attn, Wproj_ca, bproj_ca, p_x1, p_x2,
        MX, Dm, Dm, Dm, Dm, Dm, 0,0,0,0,0,0, 1, 1.0f);

    // ---- 14) ln3 = LN(x2)
    ln_kernel<<<MX, 256>>>(p_x2, g3, b3, p_ln);

    // ---- 15) ffh = gelu(ln3 @ Wff1 + bff1)
    gemm_kernel<5,false><<<ggrid(MX, DFF, 1), 256>>>(
        p_ln, Wff1, bff1, nullptr, p_ff,
        MX, DFF, Dm, Dm, DFF, DFF, 0,0,0,0,0,0, 1, 1.0f);

    // ---- 16) out = x2 + ffh @ Wff2 + bff2
    gemm_kernel<3,false><<<ggrid(MX, Dm, 1), 256>>>(
        p_ff, Wff2, bff2, p_x2, out,
        MX, Dm, DFF, DFF, Dm, Dm, 0,0,0,0,0,0, 1, 1.0f);
}